// round 1
// baseline (speedup 1.0000x reference)
#include <cuda_runtime.h>
#include <math.h>

#define PI_F 3.14159265358979f

static __device__ __forceinline__ float clampf(float x, float lo, float hi) {
    return fminf(fmaxf(x, lo), hi);
}

// One warp per row. Lane l owns k in [8l, 8l+8).
// Analytic gradient:
//   S = sum_k k * w_k,  w_k = (1/8)[0.5*(zre*s - zim*c) + s*c*(c^2-s^2)/24576]
//   g_th = (pi^2/3) * cos(th_rad) * (1-T0^2) * S
//   g_r  = -0.4*pi * (1-T1^2) * S
__global__ void __launch_bounds__(256) refiner_kernel(
    const float* __restrict__ z_real,
    const float* __restrict__ z_imag,
    const float* __restrict__ theta0_deg,
    const float* __restrict__ r0_m,
    const float* __restrict__ a_th_raw,
    const float* __restrict__ a_r_raw,
    const float* __restrict__ l_th_raw,
    const float* __restrict__ l_r_raw,
    float* __restrict__ out,
    int B)
{
    __shared__ float s_ath[10], s_ar[10], s_lth[10], s_lr[10];
    int tid = threadIdx.x;
    if (tid < 10) {
        // softplus + clip, hoisted out of the per-row iteration loop
        s_ath[tid] = clampf(log1pf(expf(a_th_raw[tid])), 1e-6f, 0.2f);
        s_ar[tid]  = clampf(log1pf(expf(a_r_raw[tid])),  1e-6f, 0.2f);
        s_lth[tid] = clampf(log1pf(expf(l_th_raw[tid])), 1e-6f, 1.0f);
        s_lr[tid]  = clampf(log1pf(expf(l_r_raw[tid])),  1e-6f, 1.0f);
    }
    __syncthreads();

    int warp = (int)((blockIdx.x * blockDim.x + tid) >> 5);
    int lane = tid & 31;
    if (warp >= B) return;

    // Load z (values are +-1) once into registers: 8 consecutive k per lane.
    const float4* zr4 = reinterpret_cast<const float4*>(z_real + (size_t)warp * 256) + lane * 2;
    const float4* zi4 = reinterpret_cast<const float4*>(z_imag + (size_t)warp * 256) + lane * 2;
    float4 a0 = zr4[0], a1 = zr4[1];
    float4 b0 = zi4[0], b1 = zi4[1];
    float zre[8] = {a0.x, a0.y, a0.z, a0.w, a1.x, a1.y, a1.z, a1.w};
    float zim[8] = {b0.x, b0.y, b0.z, b0.w, b1.x, b1.y, b1.z, b1.w};

    const float EPS = 1e-6f;
    float th0 = theta0_deg[warp];
    float rr0 = r0_m[warp];
    // map_theta_r_to_u: mid=0, half=60, R in [0,2000]
    float y = clampf(th0 * (1.0f / 60.0f), -1.0f + EPS, 1.0f - EPS);
    float u0 = atanhf(y);
    float sfrac = clampf(rr0 * (1.0f / 2000.0f), EPS, 1.0f - EPS);
    float u1 = atanhf(2.0f * sfrac - 1.0f);

    const float k0f = (float)(lane * 8);

    #pragma unroll 1
    for (int t = 0; t < 10; t++) {
        float T0 = tanhf(u0);
        float T1 = tanhf(u1);
        float th_rad = T0 * (60.0f * PI_F / 180.0f);
        float r = 1000.0f * (T1 + 1.0f);
        float sth, cth;
        sincosf(th_rad, &sth, &cth);
        // P = 2*pi*(SPATIAL*sin(th) - RANGE_C*r), SPATIAL=0.5, RANGE_C=2e-4
        float P = 2.0f * PI_F * fmaf(-2e-4f, r, 0.5f * sth);
        float sP, cP;
        sincosf(P, &sP, &cP);
        float s, c;
        sincosf(k0f * P, &s, &c);

        float acc1 = 0.0f;  // sum k*(zre*s - zim*c)
        float acc2 = 0.0f;  // sum k*s*c*(c^2-s^2)
        float kf = k0f;
        #pragma unroll
        for (int j = 0; j < 8; j++) {
            float m  = fmaf(zre[j], s, -(zim[j] * c));
            acc1 = fmaf(kf, m, acc1);
            float sc = s * c;
            float d  = fmaf(c, c, -(s * s));
            acc2 = fmaf(kf, sc * d, acc2);
            // rotate (s,c) by P: angle recurrence, no MUFU
            float sn = fmaf(s, cP, c * sP);
            float cn = fmaf(c, cP, -(s * sP));
            s = sn; c = cn;
            kf += 1.0f;
        }
        // S = acc1/16 + acc2/196608  (folds the 1/8 prefactor)
        float v = fmaf(acc1, 0.0625f, acc2 * (1.0f / 196608.0f));
        #pragma unroll
        for (int o = 16; o > 0; o >>= 1)
            v += __shfl_xor_sync(0xffffffffu, v, o);

        float sech0 = fmaf(-T0, T0, 1.0f);
        float sech1 = fmaf(-T1, T1, 1.0f);
        float g_th = (PI_F * PI_F / 3.0f) * cth * sech0 * v;
        float g_r  = (-0.4f * PI_F) * sech1 * v;

        float den_th = fmaxf(fabsf(g_th), 1e-6f) + s_lth[t];
        float den_r  = fmaxf(fabsf(g_r),  1e-6f) + s_lr[t];
        float st_th = clampf(s_ath[t] * g_th / den_th, -0.1f, 0.1f);
        float st_r  = clampf(s_ar[t]  * g_r  / den_r,  -0.1f, 0.1f);
        u0 -= st_th;
        u1 -= st_r;
    }

    if (lane == 0) {
        float T0 = tanhf(u0);
        float T1 = tanhf(u1);
        float2 o;
        o.x = 60.0f * T0;
        o.y = 1000.0f * (T1 + 1.0f);
        reinterpret_cast<float2*>(out)[warp] = o;
    }
}

extern "C" void kernel_launch(void* const* d_in, const int* in_sizes, int n_in,
                              void* d_out, int out_size) {
    const float* z_real    = (const float*)d_in[0];
    const float* z_imag    = (const float*)d_in[1];
    const float* theta0    = (const float*)d_in[2];
    const float* r0        = (const float*)d_in[3];
    const float* a_th_raw  = (const float*)d_in[4];
    const float* a_r_raw   = (const float*)d_in[5];
    const float* l_th_raw  = (const float*)d_in[6];
    const float* l_r_raw   = (const float*)d_in[7];
    float* out = (float*)d_out;

    int B = in_sizes[2];  // theta0 element count = batch size
    int threads = 256;
    int blocks = (B * 32 + threads - 1) / threads;
    refiner_kernel<<<blocks, threads>>>(z_real, z_imag, theta0, r0,
                                        a_th_raw, a_r_raw, l_th_raw, l_r_raw,
                                        out, B);
}

// round 2
// speedup vs baseline: 1.2613x; 1.2613x over previous
#include <cuda_runtime.h>
#include <math.h>

#define PI_F  3.14159265358979f
#define TWOPI 6.28318530717959f

typedef unsigned long long u64;

static __device__ __forceinline__ float clampf(float x, float lo, float hi) {
    return fminf(fmaxf(x, lo), hi);
}

// ---- packed f32x2 helpers (Blackwell FFMA2 path, PTX-only) ----
static __device__ __forceinline__ u64 pk2(float lo, float hi) {
    u64 r; asm("mov.b64 %0,{%1,%2};" : "=l"(r) : "f"(lo), "f"(hi)); return r;
}
static __device__ __forceinline__ void upk2(u64 v, float& lo, float& hi) {
    asm("mov.b64 {%0,%1},%2;" : "=f"(lo), "=f"(hi) : "l"(v));
}
static __device__ __forceinline__ u64 f2fma(u64 a, u64 b, u64 c) {
    u64 d; asm("fma.rn.f32x2 %0,%1,%2,%3;" : "=l"(d) : "l"(a), "l"(b), "l"(c)); return d;
}
static __device__ __forceinline__ u64 f2mul(u64 a, u64 b) {
    u64 d; asm("mul.rn.f32x2 %0,%1,%2;" : "=l"(d) : "l"(a), "l"(b)); return d;
}
static __device__ __forceinline__ u64 f2add(u64 a, u64 b) {
    u64 d; asm("add.rn.f32x2 %0,%1,%2;" : "=l"(d) : "l"(a), "l"(b)); return d;
}

// fast tanh: |x| <= ~3 in this problem, no overflow risk
static __device__ __forceinline__ float tanh_fast(float x) {
    float e = __expf(2.0f * x);
    return fmaf(-2.0f, __fdividef(1.0f, e + 1.0f), 1.0f);
}

// One warp per row. Lane l owns k in [8l, 8l+8) as 4 packed pairs.
__global__ void __launch_bounds__(256) refiner_kernel(
    const float* __restrict__ z_real,
    const float* __restrict__ z_imag,
    const float* __restrict__ theta0_deg,
    const float* __restrict__ r0_m,
    const float* __restrict__ a_th_raw,
    const float* __restrict__ a_r_raw,
    const float* __restrict__ l_th_raw,
    const float* __restrict__ l_r_raw,
    float* __restrict__ out,
    int B)
{
    __shared__ float s_ath[10], s_ar[10], s_lth[10], s_lr[10];
    int tid = threadIdx.x;
    if (tid < 10) {
        s_ath[tid] = clampf(log1pf(expf(a_th_raw[tid])), 1e-6f, 0.2f);
        s_ar[tid]  = clampf(log1pf(expf(a_r_raw[tid])),  1e-6f, 0.2f);
        s_lth[tid] = clampf(log1pf(expf(l_th_raw[tid])), 1e-6f, 1.0f);
        s_lr[tid]  = clampf(log1pf(expf(l_r_raw[tid])),  1e-6f, 1.0f);
    }
    __syncthreads();

    int warp = (int)((blockIdx.x * blockDim.x + tid) >> 5);
    int lane = tid & 31;
    if (warp >= B) return;

    // Load z (+-1) once: 8 consecutive k per lane, packed as 4 pairs.
    const float4* zr4 = reinterpret_cast<const float4*>(z_real + (size_t)warp * 256) + lane * 2;
    const float4* zi4 = reinterpret_cast<const float4*>(z_imag + (size_t)warp * 256) + lane * 2;
    float4 a0v = zr4[0], a1v = zr4[1];
    float4 b0v = zi4[0], b1v = zi4[1];
    u64 zre2[4], nzim2[4];
    zre2[0] = pk2(a0v.x, a0v.y);  zre2[1] = pk2(a0v.z, a0v.w);
    zre2[2] = pk2(a1v.x, a1v.y);  zre2[3] = pk2(a1v.z, a1v.w);
    nzim2[0] = pk2(-b0v.x, -b0v.y);  nzim2[1] = pk2(-b0v.z, -b0v.w);
    nzim2[2] = pk2(-b1v.x, -b1v.y);  nzim2[3] = pk2(-b1v.z, -b1v.w);

    const float EPS = 1e-6f;
    float th0 = theta0_deg[warp];
    float rr0 = r0_m[warp];
    float y = clampf(th0 * (1.0f / 60.0f), -1.0f + EPS, 1.0f - EPS);
    float u0 = atanhf(y);
    float sfrac = clampf(rr0 * (1.0f / 2000.0f), EPS, 1.0f - EPS);
    float u1 = atanhf(2.0f * sfrac - 1.0f);

    const float k0f = (float)(lane * 8);
    const u64 NEG2C = pk2(-2.0f, -2.0f);
    const u64 ONE2  = pk2(1.0f, 1.0f);
    const u64 TWO2  = pk2(2.0f, 2.0f);

    #pragma unroll 1
    for (int t = 0; t < 10; t++) {
        float T0 = tanh_fast(u0);
        float T1 = tanh_fast(u1);
        float th_rad = T0 * (60.0f * PI_F / 180.0f);
        // phase/(2*pi) per unit k:  q = 0.5*sin(th) - 2e-4*r,  r = 1000*(T1+1)
        float sth, cth;
        sincosf(th_rad, &sth, &cth);   // accurate: error here amplifies x778 into phase
        float q = fmaf(-0.2f, T1 + 1.0f, 0.5f * sth);

        // P reduced to [-pi, pi]
        float Pr = TWOPI * (q - rintf(q));
        float sP, cP;
        __sincosf(Pr, &sP, &cP);
        // rotation by 2P (double-angle, no extra MUFU)
        float s2P = 2.0f * sP * cP;
        float c2P = fmaf(-2.0f * sP, sP, 1.0f);
        u64 c2P2  = pk2(c2P, c2P);
        u64 s2P2  = pk2(s2P, s2P);
        u64 ns2P2 = pk2(-s2P, -s2P);

        // starting angle for this lane's first k, reduced to [-pi, pi]
        float f = k0f * q;
        float a0 = TWOPI * (f - rintf(f));
        float s0, c0;
        __sincosf(a0, &s0, &c0);
        float s1 = fmaf(s0, cP, c0 * sP);
        float c1 = fmaf(c0, cP, -(s0 * sP));

        u64 s2 = pk2(s0, s1);
        u64 c2 = pk2(c0, c1);
        u64 k2 = pk2(k0f, k0f + 1.0f);
        u64 acc1 = pk2(0.0f, 0.0f);
        u64 acc2 = acc1;

        #pragma unroll
        for (int j = 0; j < 4; j++) {
            // m = zre*s - zim*c
            u64 m2 = f2fma(zre2[j], s2, f2mul(nzim2[j], c2));
            acc1 = f2fma(k2, m2, acc1);
            // s*c*(c^2 - s^2) = (s*c)*(1 - 2 s^2)
            u64 sc2 = f2mul(s2, c2);
            u64 ss2 = f2mul(s2, s2);
            u64 d2  = f2fma(ss2, NEG2C, ONE2);
            acc2 = f2fma(k2, f2mul(sc2, d2), acc2);
            // rotate (s,c) by 2P
            u64 sn = f2fma(s2, c2P2, f2mul(c2, s2P2));
            u64 cn = f2fma(c2, c2P2, f2mul(s2, ns2P2));
            s2 = sn; c2 = cn;
            k2 = f2add(k2, TWO2);
        }

        // v = acc1/16 + acc2/196608 (folds the 1/8 prefactor)
        u64 v2 = f2fma(acc1, pk2(0.0625f, 0.0625f),
                       f2mul(acc2, pk2(1.0f / 196608.0f, 1.0f / 196608.0f)));
        float vlo, vhi;
        upk2(v2, vlo, vhi);
        float v = vlo + vhi;
        #pragma unroll
        for (int o = 16; o > 0; o >>= 1)
            v += __shfl_xor_sync(0xffffffffu, v, o);

        float sech0 = fmaf(-T0, T0, 1.0f);
        float sech1 = fmaf(-T1, T1, 1.0f);
        float g_th = (PI_F * PI_F / 3.0f) * cth * sech0 * v;
        float g_r  = (-0.4f * PI_F) * sech1 * v;

        float den_th = fmaxf(fabsf(g_th), 1e-6f) + s_lth[t];
        float den_r  = fmaxf(fabsf(g_r),  1e-6f) + s_lr[t];
        float st_th = clampf(s_ath[t] * __fdividef(g_th, den_th), -0.1f, 0.1f);
        float st_r  = clampf(s_ar[t]  * __fdividef(g_r,  den_r),  -0.1f, 0.1f);
        u0 -= st_th;
        u1 -= st_r;
    }

    if (lane == 0) {
        float T0 = tanhf(u0);
        float T1 = tanhf(u1);
        float2 o;
        o.x = 60.0f * T0;
        o.y = 1000.0f * (T1 + 1.0f);
        reinterpret_cast<float2*>(out)[warp] = o;
    }
}

extern "C" void kernel_launch(void* const* d_in, const int* in_sizes, int n_in,
                              void* d_out, int out_size) {
    const float* z_real    = (const float*)d_in[0];
    const float* z_imag    = (const float*)d_in[1];
    const float* theta0    = (const float*)d_in[2];
    const float* r0        = (const float*)d_in[3];
    const float* a_th_raw  = (const float*)d_in[4];
    const float* a_r_raw   = (const float*)d_in[5];
    const float* l_th_raw  = (const float*)d_in[6];
    const float* l_r_raw   = (const float*)d_in[7];
    float* out = (float*)d_out;

    int B = in_sizes[2];
    int threads = 256;
    int blocks = (B * 32 + threads - 1) / threads;
    refiner_kernel<<<blocks, threads>>>(z_real, z_imag, theta0, r0,
                                        a_th_raw, a_r_raw, l_th_raw, l_r_raw,
                                        out, B);
}

// round 4
// speedup vs baseline: 1.5212x; 1.2061x over previous
#include <cuda_runtime.h>
#include <math.h>

#define PI_F  3.14159265358979f
#define TWOPI 6.28318530717959f

typedef unsigned long long u64;

static __device__ __forceinline__ float clampf(float x, float lo, float hi) {
    return fminf(fmaxf(x, lo), hi);
}

// ---- packed f32x2 helpers (Blackwell FFMA2 path, PTX-only) ----
static __device__ __forceinline__ u64 pk2(float lo, float hi) {
    u64 r; asm("mov.b64 %0,{%1,%2};" : "=l"(r) : "f"(lo), "f"(hi)); return r;
}
static __device__ __forceinline__ void upk2(u64 v, float& lo, float& hi) {
    asm("mov.b64 {%0,%1},%2;" : "=f"(lo), "=f"(hi) : "l"(v));
}
static __device__ __forceinline__ u64 f2fma(u64 a, u64 b, u64 c) {
    u64 d; asm("fma.rn.f32x2 %0,%1,%2,%3;" : "=l"(d) : "l"(a), "l"(b), "l"(c)); return d;
}
static __device__ __forceinline__ u64 f2mul(u64 a, u64 b) {
    u64 d; asm("mul.rn.f32x2 %0,%1,%2;" : "=l"(d) : "l"(a), "l"(b)); return d;
}
static __device__ __forceinline__ u64 f2add(u64 a, u64 b) {
    u64 d; asm("add.rn.f32x2 %0,%1,%2;" : "=l"(d) : "l"(a), "l"(b)); return d;
}

// fast tanh: |x| small here, no overflow risk
static __device__ __forceinline__ float tanh_fast(float x) {
    float e = __expf(2.0f * x);
    return fmaf(-2.0f, __fdividef(1.0f, e + 1.0f), 1.0f);
}

// One warp per row. Lane l owns k in [8l, 8l+8) as 4 packed pairs,
// split across 2 independent rotation chains (A: pairs 0,2; B: pairs 1,3).
__global__ void __launch_bounds__(256) refiner_kernel(
    const float* __restrict__ z_real,
    const float* __restrict__ z_imag,
    const float* __restrict__ theta0_deg,
    const float* __restrict__ r0_m,
    const float* __restrict__ a_th_raw,
    const float* __restrict__ a_r_raw,
    const float* __restrict__ l_th_raw,
    const float* __restrict__ l_r_raw,
    float* __restrict__ out,
    int B)
{
    __shared__ float s_ath[10], s_ar[10], s_lth[10], s_lr[10];
    int tid = threadIdx.x;
    if (tid < 10) {
        s_ath[tid] = clampf(log1pf(expf(a_th_raw[tid])), 1e-6f, 0.2f);
        s_ar[tid]  = clampf(log1pf(expf(a_r_raw[tid])),  1e-6f, 0.2f);
        s_lth[tid] = clampf(log1pf(expf(l_th_raw[tid])), 1e-6f, 1.0f);
        s_lr[tid]  = clampf(log1pf(expf(l_r_raw[tid])),  1e-6f, 1.0f);
    }
    __syncthreads();

    int warp = (int)((blockIdx.x * blockDim.x + tid) >> 5);
    int lane = tid & 31;
    if (warp >= B) return;

    // Load z (+-1) once: 8 consecutive k per lane, packed as 4 pairs.
    const float4* zr4 = reinterpret_cast<const float4*>(z_real + (size_t)warp * 256) + lane * 2;
    const float4* zi4 = reinterpret_cast<const float4*>(z_imag + (size_t)warp * 256) + lane * 2;
    float4 a0v = zr4[0], a1v = zr4[1];
    float4 b0v = zi4[0], b1v = zi4[1];
    u64 zre2[4], nzim2[4];
    zre2[0] = pk2(a0v.x, a0v.y);  zre2[1] = pk2(a0v.z, a0v.w);
    zre2[2] = pk2(a1v.x, a1v.y);  zre2[3] = pk2(a1v.z, a1v.w);
    nzim2[0] = pk2(-b0v.x, -b0v.y);  nzim2[1] = pk2(-b0v.z, -b0v.w);
    nzim2[2] = pk2(-b1v.x, -b1v.y);  nzim2[3] = pk2(-b1v.z, -b1v.w);

    const float EPS = 1e-6f;
    float th0 = theta0_deg[warp];
    float rr0 = r0_m[warp];
    float y = clampf(th0 * (1.0f / 60.0f), -1.0f + EPS, 1.0f - EPS);
    float u0 = atanhf(y);
    float sfrac = clampf(rr0 * (1.0f / 2000.0f), EPS, 1.0f - EPS);
    float u1 = atanhf(2.0f * sfrac - 1.0f);

    const float k0f = (float)(lane * 8);
    // loop-invariant packed k constants
    const u64 kA0 = pk2(k0f,        k0f + 1.0f);
    const u64 kB0 = pk2(k0f + 2.0f, k0f + 3.0f);
    const u64 kA1 = pk2(k0f + 4.0f, k0f + 5.0f);
    const u64 kB1 = pk2(k0f + 6.0f, k0f + 7.0f);
    const u64 NEG2C = pk2(-2.0f, -2.0f);
    const u64 ONE2  = pk2(1.0f, 1.0f);
    const u64 C16   = pk2(0.0625f, 0.0625f);
    const u64 CCORR = pk2(1.0f / 196608.0f, 1.0f / 196608.0f);

    #pragma unroll 1
    for (int t = 0; t < 10; t++) {
        float T0 = tanh_fast(u0);
        float T1 = tanh_fast(u1);
        float th_rad = T0 * (60.0f * PI_F / 180.0f);
        float sth, cth;
        __sincosf(th_rad, &sth, &cth);   // arg in [-1.05,1.05]: MUFU fast path
        // q = phase/(2*pi) per unit k = 0.5*sin(th) - 2e-4*r,  r = 1000*(T1+1)
        float q = fmaf(-0.2f, T1 + 1.0f, 0.5f * sth);

        // P reduced to [-pi, pi]
        float Pr = TWOPI * (q - rintf(q));
        float sP, cP;
        __sincosf(Pr, &sP, &cP);
        // 2P and 4P rotations via double-angle (no extra MUFU)
        float s2P = 2.0f * sP * cP;
        float c2P = fmaf(-2.0f * sP, sP, 1.0f);
        float s4P = 2.0f * s2P * c2P;
        float c4P = fmaf(-2.0f * s2P, s2P, 1.0f);
        u64 c4P2  = pk2(c4P, c4P);
        u64 s4P2  = pk2(s4P, s4P);
        u64 ns4P2 = pk2(-s4P, -s4P);

        // chain A start: angles (k0*2pi*q, (k0+1)*2pi*q), reduced
        float f = k0f * q;
        float a0 = TWOPI * (f - rintf(f));
        float s0, c0;
        __sincosf(a0, &s0, &c0);
        float s1 = fmaf(s0, cP, c0 * sP);
        float c1 = fmaf(c0, cP, -(s0 * sP));
        u64 sA = pk2(s0, s1);
        u64 cA = pk2(c0, c1);
        // chain B start = chain A rotated by 2P
        u64 c2P2  = pk2(c2P, c2P);
        u64 s2P2  = pk2(s2P, s2P);
        u64 ns2P2 = pk2(-s2P, -s2P);
        u64 sB = f2fma(sA, c2P2, f2mul(cA, s2P2));
        u64 cB = f2fma(cA, c2P2, f2mul(sA, ns2P2));

        u64 acc1A = pk2(0.0f, 0.0f), acc1B = acc1A;
        u64 acc2A = acc1A,           acc2B = acc1A;

        // ---- pair 0 (chain A), pair 1 (chain B) ----
        {
            u64 mA = f2fma(zre2[0], sA, f2mul(nzim2[0], cA));
            acc1A = f2fma(kA0, mA, acc1A);
            u64 scA = f2mul(sA, cA);
            u64 dA  = f2fma(f2mul(sA, sA), NEG2C, ONE2);
            acc2A = f2fma(kA0, f2mul(scA, dA), acc2A);

            u64 mB = f2fma(zre2[1], sB, f2mul(nzim2[1], cB));
            acc1B = f2fma(kB0, mB, acc1B);
            u64 scB = f2mul(sB, cB);
            u64 dB  = f2fma(f2mul(sB, sB), NEG2C, ONE2);
            acc2B = f2fma(kB0, f2mul(scB, dB), acc2B);

            // rotate both chains by 4P (independent chains -> 2x ILP)
            u64 snA = f2fma(sA, c4P2, f2mul(cA, s4P2));
            u64 cnA = f2fma(cA, c4P2, f2mul(sA, ns4P2));
            u64 snB = f2fma(sB, c4P2, f2mul(cB, s4P2));
            u64 cnB = f2fma(cB, c4P2, f2mul(sB, ns4P2));
            sA = snA; cA = cnA; sB = snB; cB = cnB;
        }
        // ---- pair 2 (chain A), pair 3 (chain B); no trailing rotation ----
        {
            u64 mA = f2fma(zre2[2], sA, f2mul(nzim2[2], cA));
            acc1A = f2fma(kA1, mA, acc1A);
            u64 scA = f2mul(sA, cA);
            u64 dA  = f2fma(f2mul(sA, sA), NEG2C, ONE2);
            acc2A = f2fma(kA1, f2mul(scA, dA), acc2A);

            u64 mB = f2fma(zre2[3], sB, f2mul(nzim2[3], cB));
            acc1B = f2fma(kB1, mB, acc1B);
            u64 scB = f2mul(sB, cB);
            u64 dB  = f2fma(f2mul(sB, sB), NEG2C, ONE2);
            acc2B = f2fma(kB1, f2mul(scB, dB), acc2B);
        }

        u64 acc1 = f2add(acc1A, acc1B);
        u64 acc2 = f2add(acc2A, acc2B);
        // v = acc1/16 + acc2/196608 (folds the 1/8 prefactor)
        u64 v2 = f2fma(acc1, C16, f2mul(acc2, CCORR));
        float vlo, vhi;
        upk2(v2, vlo, vhi);
        float v = vlo + vhi;
        #pragma unroll
        for (int o = 16; o > 0; o >>= 1)
            v += __shfl_xor_sync(0xffffffffu, v, o);

        float sech0 = fmaf(-T0, T0, 1.0f);
        float sech1 = fmaf(-T1, T1, 1.0f);
        float g_th = (PI_F * PI_F / 3.0f) * cth * sech0 * v;
        float g_r  = (-0.4f * PI_F) * sech1 * v;

        float den_th = fmaxf(fabsf(g_th), 1e-6f) + s_lth[t];
        float den_r  = fmaxf(fabsf(g_r),  1e-6f) + s_lr[t];
        float st_th = clampf(s_ath[t] * __fdividef(g_th, den_th), -0.1f, 0.1f);
        float st_r  = clampf(s_ar[t]  * __fdividef(g_r,  den_r),  -0.1f, 0.1f);
        u0 -= st_th;
        u1 -= st_r;
    }

    if (lane == 0) {
        float T0 = tanhf(u0);
        float T1 = tanhf(u1);
        float2 o;
        o.x = 60.0f * T0;
        o.y = 1000.0f * (T1 + 1.0f);
        reinterpret_cast<float2*>(out)[warp] = o;
    }
}

extern "C" void kernel_launch(void* const* d_in, const int* in_sizes, int n_in,
                              void* d_out, int out_size) {
    const float* z_real    = (const float*)d_in[0];
    const float* z_imag    = (const float*)d_in[1];
    const float* theta0    = (const float*)d_in[2];
    const float* r0        = (const float*)d_in[3];
    const float* a_th_raw  = (const float*)d_in[4];
    const float* a_r_raw   = (const float*)d_in[5];
    const float* l_th_raw  = (const float*)d_in[6];
    const float* l_r_raw   = (const float*)d_in[7];
    float* out = (float*)d_out;

    int B = in_sizes[2];
    int threads = 256;
    int blocks = (B * 32 + threads - 1) / threads;
    refiner_kernel<<<blocks, threads>>>(z_real, z_imag, theta0, r0,
                                        a_th_raw, a_r_raw, l_th_raw, l_r_raw,
                                        out, B);
}

// round 5
// speedup vs baseline: 2.5277x; 1.6616x over previous
#include <cuda_runtime.h>
#include <math.h>

#define PI_F  3.14159265358979f
#define TWOPI 6.28318530717959f

typedef unsigned long long u64;

static __device__ __forceinline__ float clampf(float x, float lo, float hi) {
    return fminf(fmaxf(x, lo), hi);
}

// ---- packed f32x2 helpers (Blackwell FFMA2 path, PTX-only) ----
static __device__ __forceinline__ u64 pk2(float lo, float hi) {
    u64 r; asm("mov.b64 %0,{%1,%2};" : "=l"(r) : "f"(lo), "f"(hi)); return r;
}
static __device__ __forceinline__ void upk2(u64 v, float& lo, float& hi) {
    asm("mov.b64 {%0,%1},%2;" : "=f"(lo), "=f"(hi) : "l"(v));
}
static __device__ __forceinline__ u64 f2fma(u64 a, u64 b, u64 c) {
    u64 d; asm("fma.rn.f32x2 %0,%1,%2,%3;" : "=l"(d) : "l"(a), "l"(b), "l"(c)); return d;
}
static __device__ __forceinline__ u64 f2mul(u64 a, u64 b) {
    u64 d; asm("mul.rn.f32x2 %0,%1,%2;" : "=l"(d) : "l"(a), "l"(b)); return d;
}
static __device__ __forceinline__ u64 f2add(u64 a, u64 b) {
    u64 d; asm("add.rn.f32x2 %0,%1,%2;" : "=l"(d) : "l"(a), "l"(b)); return d;
}

// fast tanh: |x| small here, no overflow risk
static __device__ __forceinline__ float tanh_fast(float x) {
    float e = __expf(2.0f * x);
    return fmaf(-2.0f, __fdividef(1.0f, e + 1.0f), 1.0f);
}

// TWO rows per warp: lanes 0-15 -> row 2w, lanes 16-31 -> row 2w+1.
// Each lane owns 16 consecutive k (8 packed pairs), k0 = 16*(lane&15).
// k (and the -zim sign) are pre-multiplied into the z registers: the inner
// loop is 2 FFMA2 per pair. Two rotation chains (A: even pairs, B: odd pairs)
// advance by 4P; acc2 Taylor-correction term dropped (<=3e-4 rel on g).
__global__ void __launch_bounds__(256) refiner_kernel(
    const float* __restrict__ z_real,
    const float* __restrict__ z_imag,
    const float* __restrict__ theta0_deg,
    const float* __restrict__ r0_m,
    const float* __restrict__ a_th_raw,
    const float* __restrict__ a_r_raw,
    const float* __restrict__ l_th_raw,
    const float* __restrict__ l_r_raw,
    float* __restrict__ out,
    int B)
{
    __shared__ float s_ath[10], s_ar[10], s_lth[10], s_lr[10];
    int tid = threadIdx.x;
    if (tid < 10) {
        s_ath[tid] = clampf(log1pf(expf(a_th_raw[tid])), 1e-6f, 0.2f);
        s_ar[tid]  = clampf(log1pf(expf(a_r_raw[tid])),  1e-6f, 0.2f);
        s_lth[tid] = clampf(log1pf(expf(l_th_raw[tid])), 1e-6f, 1.0f);
        s_lr[tid]  = clampf(log1pf(expf(l_r_raw[tid])),  1e-6f, 1.0f);
    }
    __syncthreads();

    int gwarp = (int)((blockIdx.x * blockDim.x + tid) >> 5);
    int lane  = tid & 31;
    int half  = lane >> 4;      // which row of the pair
    int hl    = lane & 15;      // lane within the 16-lane row group
    int row   = gwarp * 2 + half;
    if (row >= B) return;

    const float k0f = (float)(hl * 16);

    // Load this lane's 16 z values per array and fold k (and -1 for zim) in.
    const float4* zr4 = reinterpret_cast<const float4*>(z_real + (size_t)row * 256) + hl * 4;
    const float4* zi4 = reinterpret_cast<const float4*>(z_imag + (size_t)row * 256) + hl * 4;
    u64 kzre[8], knzim[8];
    {
        float zr[16], zi[16];
        #pragma unroll
        for (int q4 = 0; q4 < 4; q4++) {
            float4 a = zr4[q4], b = zi4[q4];
            zr[q4*4+0]=a.x; zr[q4*4+1]=a.y; zr[q4*4+2]=a.z; zr[q4*4+3]=a.w;
            zi[q4*4+0]=b.x; zi[q4*4+1]=b.y; zi[q4*4+2]=b.z; zi[q4*4+3]=b.w;
        }
        #pragma unroll
        for (int j = 0; j < 8; j++) {
            float ka = k0f + (float)(2*j);
            float kb = ka + 1.0f;
            kzre[j]  = pk2(ka * zr[2*j],  kb * zr[2*j+1]);
            knzim[j] = pk2(-ka * zi[2*j], -kb * zi[2*j+1]);
        }
    }

    const float EPS = 1e-6f;
    float th0 = theta0_deg[row];
    float rr0 = r0_m[row];
    float y = clampf(th0 * (1.0f / 60.0f), -1.0f + EPS, 1.0f - EPS);
    float u0 = atanhf(y);
    float sfrac = clampf(rr0 * (1.0f / 2000.0f), EPS, 1.0f - EPS);
    float u1 = atanhf(2.0f * sfrac - 1.0f);

    // gradient prefactors with the 1/16 of S folded in
    const float C_GTH = (PI_F * PI_F / 3.0f) / 16.0f;   // * cth * sech0 * v
    const float C_GR  = -(0.4f * PI_F) / 16.0f;         // * sech1 * v

    #pragma unroll 1
    for (int t = 0; t < 10; t++) {
        float T0 = tanh_fast(u0);
        float T1 = tanh_fast(u1);
        float th_rad = T0 * (60.0f * PI_F / 180.0f);
        float sth, cth;
        __sincosf(th_rad, &sth, &cth);
        // q = 0.5*sin(th) - 2e-4*r,  r = 1000*(T1+1)
        float q = fmaf(-0.2f, T1 + 1.0f, 0.5f * sth);

        float Pr = TWOPI * (q - rintf(q));
        float sP, cP;
        __sincosf(Pr, &sP, &cP);
        float s2P = 2.0f * sP * cP;
        float c2P = fmaf(-2.0f * sP, sP, 1.0f);
        float s4P = 2.0f * s2P * c2P;
        float c4P = fmaf(-2.0f * s2P, s2P, 1.0f);
        u64 c4P2  = pk2(c4P, c4P);
        u64 s4P2  = pk2(s4P, s4P);
        u64 ns4P2 = pk2(-s4P, -s4P);

        // chain A start: angles for k0, k0+1
        float f = k0f * q;
        float a0 = TWOPI * (f - rintf(f));
        float s0, c0;
        __sincosf(a0, &s0, &c0);
        float s1 = fmaf(s0, cP, c0 * sP);
        float c1 = fmaf(c0, cP, -(s0 * sP));
        u64 sA = pk2(s0, s1);
        u64 cA = pk2(c0, c1);
        // chain B = A rotated by 2P (k0+2, k0+3)
        u64 c2P2  = pk2(c2P, c2P);
        u64 s2P2  = pk2(s2P, s2P);
        u64 ns2P2 = pk2(-s2P, -s2P);
        u64 sB = f2fma(sA, c2P2, f2mul(cA, s2P2));
        u64 cB = f2fma(cA, c2P2, f2mul(sA, ns2P2));

        u64 accS = pk2(0.0f, 0.0f);
        u64 accC = accS;

        #pragma unroll
        for (int m = 0; m < 4; m++) {
            accS = f2fma(kzre[2*m],   sA, accS);
            accC = f2fma(knzim[2*m],  cA, accC);
            accS = f2fma(kzre[2*m+1], sB, accS);
            accC = f2fma(knzim[2*m+1],cB, accC);
            if (m < 3) {
                u64 snA = f2fma(sA, c4P2, f2mul(cA, s4P2));
                u64 cnA = f2fma(cA, c4P2, f2mul(sA, ns4P2));
                u64 snB = f2fma(sB, c4P2, f2mul(cB, s4P2));
                u64 cnB = f2fma(cB, c4P2, f2mul(sB, ns4P2));
                sA = snA; cA = cnA; sB = snB; cB = cnB;
            }
        }

        u64 v2 = f2add(accS, accC);
        float vlo, vhi;
        upk2(v2, vlo, vhi);
        float v = vlo + vhi;
        // 4-level butterfly within the 16-lane row group
        #pragma unroll
        for (int o = 8; o > 0; o >>= 1)
            v += __shfl_xor_sync(0xffffffffu, v, o);

        float sech0 = fmaf(-T0, T0, 1.0f);
        float sech1 = fmaf(-T1, T1, 1.0f);
        float g_th = C_GTH * cth * sech0 * v;
        float g_r  = C_GR * sech1 * v;

        float den_th = fmaxf(fabsf(g_th), 1e-6f) + s_lth[t];
        float den_r  = fmaxf(fabsf(g_r),  1e-6f) + s_lr[t];
        float st_th = clampf(s_ath[t] * __fdividef(g_th, den_th), -0.1f, 0.1f);
        float st_r  = clampf(s_ar[t]  * __fdividef(g_r,  den_r),  -0.1f, 0.1f);
        u0 -= st_th;
        u1 -= st_r;
    }

    if (hl == 0) {
        float T0 = tanhf(u0);
        float T1 = tanhf(u1);
        float2 o;
        o.x = 60.0f * T0;
        o.y = 1000.0f * (T1 + 1.0f);
        reinterpret_cast<float2*>(out)[row] = o;
    }
}

extern "C" void kernel_launch(void* const* d_in, const int* in_sizes, int n_in,
                              void* d_out, int out_size) {
    const float* z_real    = (const float*)d_in[0];
    const float* z_imag    = (const float*)d_in[1];
    const float* theta0    = (const float*)d_in[2];
    const float* r0        = (const float*)d_in[3];
    const float* a_th_raw  = (const float*)d_in[4];
    const float* a_r_raw   = (const float*)d_in[5];
    const float* l_th_raw  = (const float*)d_in[6];
    const float* l_r_raw   = (const float*)d_in[7];
    float* out = (float*)d_out;

    int B = in_sizes[2];
    int nwarps = (B + 1) / 2;               // 2 rows per warp
    int threads = 256;
    int blocks = (nwarps * 32 + threads - 1) / threads;
    refiner_kernel<<<blocks, threads>>>(z_real, z_imag, theta0, r0,
                                        a_th_raw, a_r_raw, l_th_raw, l_r_raw,
                                        out, B);
}

// round 6
// speedup vs baseline: 2.7219x; 1.0769x over previous
#include <cuda_runtime.h>
#include <math.h>

#define PI_F  3.14159265358979f
#define TWOPI 6.28318530717959f

typedef unsigned long long u64;

static __device__ __forceinline__ float clampf(float x, float lo, float hi) {
    return fminf(fmaxf(x, lo), hi);
}

// ---- packed f32x2 helpers (Blackwell FFMA2 path, PTX-only) ----
static __device__ __forceinline__ u64 pk2(float lo, float hi) {
    u64 r; asm("mov.b64 %0,{%1,%2};" : "=l"(r) : "f"(lo), "f"(hi)); return r;
}
static __device__ __forceinline__ void upk2(u64 v, float& lo, float& hi) {
    asm("mov.b64 {%0,%1},%2;" : "=f"(lo), "=f"(hi) : "l"(v));
}
static __device__ __forceinline__ u64 f2fma(u64 a, u64 b, u64 c) {
    u64 d; asm("fma.rn.f32x2 %0,%1,%2,%3;" : "=l"(d) : "l"(a), "l"(b), "l"(c)); return d;
}
static __device__ __forceinline__ u64 f2add(u64 a, u64 b) {
    u64 d; asm("add.rn.f32x2 %0,%1,%2;" : "=l"(d) : "l"(a), "l"(b)); return d;
}

// fast tanh: |x| small here, no overflow risk
static __device__ __forceinline__ float tanh_fast(float x) {
    float e = __expf(2.0f * x);
    return fmaf(-2.0f, __fdividef(1.0f, e + 1.0f), 1.0f);
}

// TWO rows per warp: lanes 0-15 -> row 2w, lanes 16-31 -> row 2w+1.
// Each lane owns 16 consecutive k (8 packed pairs), k0 = 16*(lane&15).
// k (and signs) pre-multiplied into z registers. Packed sin/cos pairs advance
// via the Chebyshev three-term recurrence w_{m+1} = (+-2cos2P)*w_m + w_{m-1}
// with the epsilon=(+,+,-,-) sign pattern folded into the k*z constants, so
// every inner op is a plain FFMA2 (2 per pair advance + 2 per pair accumulate).
__global__ void __launch_bounds__(256, 5) refiner_kernel(
    const float* __restrict__ z_real,
    const float* __restrict__ z_imag,
    const float* __restrict__ theta0_deg,
    const float* __restrict__ r0_m,
    const float* __restrict__ a_th_raw,
    const float* __restrict__ a_r_raw,
    const float* __restrict__ l_th_raw,
    const float* __restrict__ l_r_raw,
    float* __restrict__ out,
    int B)
{
    __shared__ float s_ath[10], s_ar[10], s_lth[10], s_lr[10];
    int tid = threadIdx.x;
    if (tid < 10) {
        s_ath[tid] = clampf(log1pf(expf(a_th_raw[tid])), 1e-6f, 0.2f);
        s_ar[tid]  = clampf(log1pf(expf(a_r_raw[tid])),  1e-6f, 0.2f);
        s_lth[tid] = clampf(log1pf(expf(l_th_raw[tid])), 1e-6f, 1.0f);
        s_lr[tid]  = clampf(log1pf(expf(l_r_raw[tid])),  1e-6f, 1.0f);
    }
    __syncthreads();

    int gwarp = (int)((blockIdx.x * blockDim.x + tid) >> 5);
    int lane  = tid & 31;
    int half  = lane >> 4;
    int hl    = lane & 15;
    int row   = gwarp * 2 + half;
    if (row >= B) return;

    const float k0f = (float)(hl * 16);

    // Load 16 z values per array; fold k, the zim minus, and the Chebyshev
    // epsilon pattern (+,+,-,- by pair index) into the constants.
    const float4* zr4 = reinterpret_cast<const float4*>(z_real + (size_t)row * 256) + hl * 4;
    const float4* zi4 = reinterpret_cast<const float4*>(z_imag + (size_t)row * 256) + hl * 4;
    u64 kzre[8], knzim[8];
    {
        float zr[16], zi[16];
        #pragma unroll
        for (int q4 = 0; q4 < 4; q4++) {
            float4 a = zr4[q4], b = zi4[q4];
            zr[q4*4+0]=a.x; zr[q4*4+1]=a.y; zr[q4*4+2]=a.z; zr[q4*4+3]=a.w;
            zi[q4*4+0]=b.x; zi[q4*4+1]=b.y; zi[q4*4+2]=b.z; zi[q4*4+3]=b.w;
        }
        #pragma unroll
        for (int j = 0; j < 8; j++) {
            float eps = ((j >> 1) & 1) ? -1.0f : 1.0f;   // +,+,-,-,+,+,-,-
            float ka = eps * (k0f + (float)(2*j));
            float kb = eps * (k0f + (float)(2*j) + 1.0f);
            kzre[j]  = pk2(ka * zr[2*j],  kb * zr[2*j+1]);
            knzim[j] = pk2(-ka * zi[2*j], -kb * zi[2*j+1]);
        }
    }

    const float EPS = 1e-6f;
    float th0 = theta0_deg[row];
    float rr0 = r0_m[row];
    float y = clampf(th0 * (1.0f / 60.0f), -1.0f + EPS, 1.0f - EPS);
    float u0 = atanhf(y);
    float sfrac = clampf(rr0 * (1.0f / 2000.0f), EPS, 1.0f - EPS);
    float u1 = atanhf(2.0f * sfrac - 1.0f);

    const float C_GTH = (PI_F * PI_F / 3.0f) / 16.0f;
    const float C_GR  = -(0.4f * PI_F) / 16.0f;

    #pragma unroll 1
    for (int t = 0; t < 10; t++) {
        float T0 = tanh_fast(u0);
        float T1 = tanh_fast(u1);
        float th_rad = T0 * (60.0f * PI_F / 180.0f);
        float sth, cth;
        __sincosf(th_rad, &sth, &cth);
        float q = fmaf(-0.2f, T1 + 1.0f, 0.5f * sth);

        float Pr = TWOPI * (q - rintf(q));
        float sP, cP;
        __sincosf(Pr, &sP, &cP);
        float twocP  = cP + cP;
        float twoc2P = fmaf(twocP, twocP, -2.0f);     // 2*cos(2P)
        u64 aP = pk2(twoc2P, twoc2P);
        u64 aN = pk2(-twoc2P, -twoc2P);

        // step coefficients computed BEFORE v (off the critical path)
        float sech0 = fmaf(-T0, T0, 1.0f);
        float sech1 = fmaf(-T1, T1, 1.0f);
        float cg_th = C_GTH * cth * sech0;
        float cg_r  = C_GR * sech1;
        float acg_th = s_ath[t] * cg_th;
        float acg_r  = s_ar[t]  * cg_r;

        // starting pairs: w0 = (s(a0), s(a0+P)), w1 = (s(a0+2P), s(a0+3P))
        float f = k0f * q;
        float a0 = TWOPI * (f - rintf(f));
        float s0_, c0_;
        __sincosf(a0, &s0_, &c0_);
        float s1_ = fmaf(s0_, cP, c0_ * sP);
        float c1_ = fmaf(c0_, cP, -(s0_ * sP));
        float s2_ = fmaf(twocP, s1_, -s0_);
        float c2_ = fmaf(twocP, c1_, -c0_);
        float s3_ = fmaf(twocP, s2_, -s1_);
        float c3_ = fmaf(twocP, c2_, -c1_);

        u64 psS = pk2(s0_, s1_), psC = pk2(c0_, c1_);   // w_0
        u64 cuS = pk2(s2_, s3_), cuC = pk2(c2_, c3_);   // w_1

        u64 accS = pk2(0.0f, 0.0f);
        u64 accC = accS;
        // m = 0, 1
        accS = f2fma(kzre[0], psS, accS);
        accC = f2fma(knzim[0], psC, accC);
        accS = f2fma(kzre[1], cuS, accS);
        accC = f2fma(knzim[1], cuC, accC);
        // m = 2..7: advance Chebyshev (alpha alternates -,+,-,+,-,+), accumulate
        #pragma unroll
        for (int m = 2; m < 8; m++) {
            u64 alpha = (m & 1) ? aP : aN;
            u64 nS = f2fma(alpha, cuS, psS);
            u64 nC = f2fma(alpha, cuC, psC);
            psS = cuS; cuS = nS;
            psC = cuC; cuC = nC;
            accS = f2fma(kzre[m], cuS, accS);
            accC = f2fma(knzim[m], cuC, accC);
        }

        u64 v2 = f2add(accS, accC);
        float vlo, vhi;
        upk2(v2, vlo, vhi);
        float v = vlo + vhi;
        #pragma unroll
        for (int o = 8; o > 0; o >>= 1)
            v += __shfl_xor_sync(0xffffffffu, v, o);

        float g_th = cg_th * v;
        float g_r  = cg_r * v;
        float den_th = fmaxf(fabsf(g_th), 1e-6f) + s_lth[t];
        float den_r  = fmaxf(fabsf(g_r),  1e-6f) + s_lr[t];
        float st_th = clampf(acg_th * v * __fdividef(1.0f, den_th), -0.1f, 0.1f);
        float st_r  = clampf(acg_r  * v * __fdividef(1.0f, den_r),  -0.1f, 0.1f);
        u0 -= st_th;
        u1 -= st_r;
    }

    if (hl == 0) {
        float T0 = tanh_fast(u0);
        float T1 = tanh_fast(u1);
        float2 o;
        o.x = 60.0f * T0;
        o.y = 1000.0f * (T1 + 1.0f);
        reinterpret_cast<float2*>(out)[row] = o;
    }
}

extern "C" void kernel_launch(void* const* d_in, const int* in_sizes, int n_in,
                              void* d_out, int out_size) {
    const float* z_real    = (const float*)d_in[0];
    const float* z_imag    = (const float*)d_in[1];
    const float* theta0    = (const float*)d_in[2];
    const float* r0        = (const float*)d_in[3];
    const float* a_th_raw  = (const float*)d_in[4];
    const float* a_r_raw   = (const float*)d_in[5];
    const float* l_th_raw  = (const float*)d_in[6];
    const float* l_r_raw   = (const float*)d_in[7];
    float* out = (float*)d_out;

    int B = in_sizes[2];
    int nwarps = (B + 1) / 2;
    int threads = 256;
    int blocks = (nwarps * 32 + threads - 1) / threads;
    refiner_kernel<<<blocks, threads>>>(z_real, z_imag, theta0, r0,
                                        a_th_raw, a_r_raw, l_th_raw, l_r_raw,
                                        out, B);
}

// round 7
// speedup vs baseline: 3.0105x; 1.1060x over previous
#include <cuda_runtime.h>
#include <math.h>

#define PI_F  3.14159265358979f
#define TWOPI 6.28318530717959f

typedef unsigned long long u64;

static __device__ __forceinline__ float clampf(float x, float lo, float hi) {
    return fminf(fmaxf(x, lo), hi);
}

// ---- packed f32x2 helpers (Blackwell FFMA2 path, PTX-only) ----
static __device__ __forceinline__ u64 pk2(float lo, float hi) {
    u64 r; asm("mov.b64 %0,{%1,%2};" : "=l"(r) : "f"(lo), "f"(hi)); return r;
}
static __device__ __forceinline__ void upk2(u64 v, float& lo, float& hi) {
    asm("mov.b64 {%0,%1},%2;" : "=f"(lo), "=f"(hi) : "l"(v));
}
static __device__ __forceinline__ u64 f2fma(u64 a, u64 b, u64 c) {
    u64 d; asm("fma.rn.f32x2 %0,%1,%2,%3;" : "=l"(d) : "l"(a), "l"(b), "l"(c)); return d;
}
static __device__ __forceinline__ u64 f2mul(u64 a, u64 b) {
    u64 d; asm("mul.rn.f32x2 %0,%1,%2;" : "=l"(d) : "l"(a), "l"(b)); return d;
}
static __device__ __forceinline__ u64 f2add(u64 a, u64 b) {
    u64 d; asm("add.rn.f32x2 %0,%1,%2;" : "=l"(d) : "l"(a), "l"(b)); return d;
}

// fast tanh: |x| small here, no overflow risk
static __device__ __forceinline__ float tanh_fast(float x) {
    float e = __expf(2.0f * x);
    return fmaf(-2.0f, __fdividef(1.0f, e + 1.0f), 1.0f);
}

// TWO rows per warp: lanes 0-15 -> row 2w, lanes 16-31 -> row 2w+1.
// Each lane owns 16 consecutive k (8 packed pairs), k0 = 16*(lane&15).
// k (and signs) pre-multiplied into z registers. Packed sin/cos pairs advance
// via the Chebyshev three-term recurrence w_{m+1} = (+-2cos2P)*w_m + w_{m-1}
// with the epsilon=(+,+,-,-) sign pattern folded into the k*z constants.
// 128-thread blocks, 9 blocks/SM: 56-reg cap fits true demand -> no spills.
__global__ void __launch_bounds__(128, 9) refiner_kernel(
    const float* __restrict__ z_real,
    const float* __restrict__ z_imag,
    const float* __restrict__ theta0_deg,
    const float* __restrict__ r0_m,
    const float* __restrict__ a_th_raw,
    const float* __restrict__ a_r_raw,
    const float* __restrict__ l_th_raw,
    const float* __restrict__ l_r_raw,
    float* __restrict__ out,
    int B)
{
    __shared__ float4 s_par[10];   // (a_th, a_r, l_th, l_r) per step: 1 LDS.128/t
    int tid = threadIdx.x;
    if (tid < 10) {
        float4 p;
        p.x = clampf(log1pf(expf(a_th_raw[tid])), 1e-6f, 0.2f);
        p.y = clampf(log1pf(expf(a_r_raw[tid])),  1e-6f, 0.2f);
        p.z = clampf(log1pf(expf(l_th_raw[tid])), 1e-6f, 1.0f);
        p.w = clampf(log1pf(expf(l_r_raw[tid])),  1e-6f, 1.0f);
        s_par[tid] = p;
    }
    __syncthreads();

    int gwarp = (int)((blockIdx.x * blockDim.x + tid) >> 5);
    int lane  = tid & 31;
    int half  = lane >> 4;
    int hl    = lane & 15;
    int row   = gwarp * 2 + half;
    if (row >= B) return;

    const float k0f = (float)(hl * 16);

    // Load 16 z values per array; fold k, the zim minus, and the Chebyshev
    // epsilon pattern (+,+,-,- by pair index) into the constants.
    const float4* zr4 = reinterpret_cast<const float4*>(z_real + (size_t)row * 256) + hl * 4;
    const float4* zi4 = reinterpret_cast<const float4*>(z_imag + (size_t)row * 256) + hl * 4;
    u64 kzre[8], knzim[8];
    {
        float zr[16], zi[16];
        #pragma unroll
        for (int q4 = 0; q4 < 4; q4++) {
            float4 a = zr4[q4], b = zi4[q4];
            zr[q4*4+0]=a.x; zr[q4*4+1]=a.y; zr[q4*4+2]=a.z; zr[q4*4+3]=a.w;
            zi[q4*4+0]=b.x; zi[q4*4+1]=b.y; zi[q4*4+2]=b.z; zi[q4*4+3]=b.w;
        }
        #pragma unroll
        for (int j = 0; j < 8; j++) {
            float eps = ((j >> 1) & 1) ? -1.0f : 1.0f;   // +,+,-,-,+,+,-,-
            float ka = eps * (k0f + (float)(2*j));
            float kb = eps * (k0f + (float)(2*j) + 1.0f);
            kzre[j]  = pk2(ka * zr[2*j],  kb * zr[2*j+1]);
            knzim[j] = pk2(-ka * zi[2*j], -kb * zi[2*j+1]);
        }
    }

    const float EPS = 1e-6f;
    float th0 = theta0_deg[row];
    float rr0 = r0_m[row];
    float y = clampf(th0 * (1.0f / 60.0f), -1.0f + EPS, 1.0f - EPS);
    float u0 = atanhf(y);
    float sfrac = clampf(rr0 * (1.0f / 2000.0f), EPS, 1.0f - EPS);
    float u1 = atanhf(2.0f * sfrac - 1.0f);

    const float C_GTH = (PI_F * PI_F / 3.0f) / 16.0f;
    const float C_GR  = -(0.4f * PI_F) / 16.0f;

    #pragma unroll 1
    for (int t = 0; t < 10; t++) {
        float4 par = s_par[t];   // a_th, a_r, l_th, l_r

        float T0 = tanh_fast(u0);
        float T1 = tanh_fast(u1);
        float th_rad = T0 * (60.0f * PI_F / 180.0f);
        float sth, cth;
        __sincosf(th_rad, &sth, &cth);
        float q = fmaf(-0.2f, T1 + 1.0f, 0.5f * sth);

        float Pr = TWOPI * (q - rintf(q));
        float sP, cP;
        __sincosf(Pr, &sP, &cP);
        float twocP  = cP + cP;
        float twoc2P = fmaf(twocP, twocP, -2.0f);     // 2*cos(2P)
        u64 aP = pk2(twoc2P, twoc2P);
        u64 aN = pk2(-twoc2P, -twoc2P);

        // step coefficients computed BEFORE v (off the critical path)
        float sech0 = fmaf(-T0, T0, 1.0f);
        float sech1 = fmaf(-T1, T1, 1.0f);
        float cg_th = C_GTH * cth * sech0;
        float cg_r  = C_GR * sech1;
        float acg_th = par.x * cg_th;
        float acg_r  = par.y * cg_r;

        // starting pairs: w0 = (s(a0), s(a0+P)), w1 = (s(a0+2P), s(a0+3P))
        float f = k0f * q;
        float a0 = TWOPI * (f - rintf(f));
        float s0_, c0_;
        __sincosf(a0, &s0_, &c0_);
        float s1_ = fmaf(s0_, cP, c0_ * sP);
        float c1_ = fmaf(c0_, cP, -(s0_ * sP));
        float s2_ = fmaf(twocP, s1_, -s0_);
        float c2_ = fmaf(twocP, c1_, -c0_);
        float s3_ = fmaf(twocP, s2_, -s1_);
        float c3_ = fmaf(twocP, c2_, -c1_);

        u64 psS = pk2(s0_, s1_), psC = pk2(c0_, c1_);   // w_0
        u64 cuS = pk2(s2_, s3_), cuC = pk2(c2_, c3_);   // w_1

        // m = 0, 1 (init accumulators with mul: no zero-pack)
        u64 accS = f2mul(kzre[0], psS);
        u64 accC = f2mul(knzim[0], psC);
        accS = f2fma(kzre[1], cuS, accS);
        accC = f2fma(knzim[1], cuC, accC);
        // m = 2..7: advance Chebyshev (alpha alternates -,+,-,+,-,+), accumulate
        #pragma unroll
        for (int m = 2; m < 8; m++) {
            u64 alpha = (m & 1) ? aP : aN;
            u64 nS = f2fma(alpha, cuS, psS);
            u64 nC = f2fma(alpha, cuC, psC);
            psS = cuS; cuS = nS;
            psC = cuC; cuC = nC;
            accS = f2fma(kzre[m], cuS, accS);
            accC = f2fma(knzim[m], cuC, accC);
        }

        u64 v2 = f2add(accS, accC);
        float vlo, vhi;
        upk2(v2, vlo, vhi);
        float v = vlo + vhi;
        #pragma unroll
        for (int o = 8; o > 0; o >>= 1)
            v += __shfl_xor_sync(0xffffffffu, v, o);

        float g_th = cg_th * v;
        float g_r  = cg_r * v;
        float den_th = fmaxf(fabsf(g_th), 1e-6f) + par.z;
        float den_r  = fmaxf(fabsf(g_r),  1e-6f) + par.w;
        float st_th = clampf(acg_th * v * __fdividef(1.0f, den_th), -0.1f, 0.1f);
        float st_r  = clampf(acg_r  * v * __fdividef(1.0f, den_r),  -0.1f, 0.1f);
        u0 -= st_th;
        u1 -= st_r;
    }

    if (hl == 0) {
        float T0 = tanh_fast(u0);
        float T1 = tanh_fast(u1);
        float2 o;
        o.x = 60.0f * T0;
        o.y = 1000.0f * (T1 + 1.0f);
        reinterpret_cast<float2*>(out)[row] = o;
    }
}

extern "C" void kernel_launch(void* const* d_in, const int* in_sizes, int n_in,
                              void* d_out, int out_size) {
    const float* z_real    = (const float*)d_in[0];
    const float* z_imag    = (const float*)d_in[1];
    const float* theta0    = (const float*)d_in[2];
    const float* r0        = (const float*)d_in[3];
    const float* a_th_raw  = (const float*)d_in[4];
    const float* a_r_raw   = (const float*)d_in[5];
    const float* l_th_raw  = (const float*)d_in[6];
    const float* l_r_raw   = (const float*)d_in[7];
    float* out = (float*)d_out;

    int B = in_sizes[2];
    int nwarps = (B + 1) / 2;
    int threads = 128;
    int blocks = (nwarps * 32 + threads - 1) / threads;
    refiner_kernel<<<blocks, threads>>>(z_real, z_imag, theta0, r0,
                                        a_th_raw, a_r_raw, l_th_raw, l_r_raw,
                                        out, B);
}

// round 8
// speedup vs baseline: 3.0337x; 1.0077x over previous
#include <cuda_runtime.h>
#include <math.h>

#define PI_F  3.14159265358979f
#define TWOPI 6.28318530717959f

typedef unsigned long long u64;

static __device__ __forceinline__ float clampf(float x, float lo, float hi) {
    return fminf(fmaxf(x, lo), hi);
}

// ---- packed f32x2 helpers (Blackwell FFMA2 path, PTX-only) ----
static __device__ __forceinline__ u64 pk2(float lo, float hi) {
    u64 r; asm("mov.b64 %0,{%1,%2};" : "=l"(r) : "f"(lo), "f"(hi)); return r;
}
static __device__ __forceinline__ void upk2(u64 v, float& lo, float& hi) {
    asm("mov.b64 {%0,%1},%2;" : "=f"(lo), "=f"(hi) : "l"(v));
}
static __device__ __forceinline__ u64 f2fma(u64 a, u64 b, u64 c) {
    u64 d; asm("fma.rn.f32x2 %0,%1,%2,%3;" : "=l"(d) : "l"(a), "l"(b), "l"(c)); return d;
}
static __device__ __forceinline__ u64 f2mul(u64 a, u64 b) {
    u64 d; asm("mul.rn.f32x2 %0,%1,%2;" : "=l"(d) : "l"(a), "l"(b)); return d;
}
static __device__ __forceinline__ u64 f2add(u64 a, u64 b) {
    u64 d; asm("add.rn.f32x2 %0,%1,%2;" : "=l"(d) : "l"(a), "l"(b)); return d;
}

// fast tanh: |x| small here, no overflow risk
static __device__ __forceinline__ float tanh_fast(float x) {
    float e = __expf(2.0f * x);
    return fmaf(-2.0f, __fdividef(1.0f, e + 1.0f), 1.0f);
}

// TWO rows per warp: lanes 0-15 -> row 2w, lanes 16-31 -> row 2w+1.
// Each lane owns 16 consecutive k (8 packed pairs), k0 = 16*(lane&15).
// k (and signs) pre-multiplied into z registers. Packed sin/cos pairs advance
// via the Chebyshev three-term recurrence w_{m+1} = (+-2cos2P)*w_m + w_{m-1}
// with the epsilon=(+,+,-,-) sign pattern folded into the k*z constants.
// 128-thread blocks, 9 blocks/SM: 56-reg cap fits true demand -> no spills.
__global__ void __launch_bounds__(128, 9) refiner_kernel(
    const float* __restrict__ z_real,
    const float* __restrict__ z_imag,
    const float* __restrict__ theta0_deg,
    const float* __restrict__ r0_m,
    const float* __restrict__ a_th_raw,
    const float* __restrict__ a_r_raw,
    const float* __restrict__ l_th_raw,
    const float* __restrict__ l_r_raw,
    float* __restrict__ out,
    int B)
{
    __shared__ float4 s_par[10];   // (a_th, a_r, l_th, l_r) per step: 1 LDS.128/t
    int tid = threadIdx.x;
    if (tid < 10) {
        float4 p;
        p.x = clampf(log1pf(expf(a_th_raw[tid])), 1e-6f, 0.2f);
        p.y = clampf(log1pf(expf(a_r_raw[tid])),  1e-6f, 0.2f);
        p.z = clampf(log1pf(expf(l_th_raw[tid])), 1e-6f, 1.0f);
        p.w = clampf(log1pf(expf(l_r_raw[tid])),  1e-6f, 1.0f);
        s_par[tid] = p;
    }
    __syncthreads();

    int gwarp = (int)((blockIdx.x * blockDim.x + tid) >> 5);
    int lane  = tid & 31;
    int half  = lane >> 4;
    int hl    = lane & 15;
    int row   = gwarp * 2 + half;
    if (row >= B) return;

    const float k0f = (float)(hl * 16);

    // Load 16 z values per array; fold k, the zim minus, and the Chebyshev
    // epsilon pattern (+,+,-,- by pair index) into the constants.
    const float4* zr4 = reinterpret_cast<const float4*>(z_real + (size_t)row * 256) + hl * 4;
    const float4* zi4 = reinterpret_cast<const float4*>(z_imag + (size_t)row * 256) + hl * 4;
    u64 kzre[8], knzim[8];
    {
        float zr[16], zi[16];
        #pragma unroll
        for (int q4 = 0; q4 < 4; q4++) {
            float4 a = zr4[q4], b = zi4[q4];
            zr[q4*4+0]=a.x; zr[q4*4+1]=a.y; zr[q4*4+2]=a.z; zr[q4*4+3]=a.w;
            zi[q4*4+0]=b.x; zi[q4*4+1]=b.y; zi[q4*4+2]=b.z; zi[q4*4+3]=b.w;
        }
        #pragma unroll
        for (int j = 0; j < 8; j++) {
            float eps = ((j >> 1) & 1) ? -1.0f : 1.0f;   // +,+,-,-,+,+,-,-
            float ka = eps * (k0f + (float)(2*j));
            float kb = eps * (k0f + (float)(2*j) + 1.0f);
            kzre[j]  = pk2(ka * zr[2*j],  kb * zr[2*j+1]);
            knzim[j] = pk2(-ka * zi[2*j], -kb * zi[2*j+1]);
        }
    }

    const float EPS = 1e-6f;
    float th0 = theta0_deg[row];
    float rr0 = r0_m[row];
    float y = clampf(th0 * (1.0f / 60.0f), -1.0f + EPS, 1.0f - EPS);
    float u0 = atanhf(y);
    float sfrac = clampf(rr0 * (1.0f / 2000.0f), EPS, 1.0f - EPS);
    float u1 = atanhf(2.0f * sfrac - 1.0f);

    const float C_GTH = (PI_F * PI_F / 3.0f) / 16.0f;
    const float C_GR  = -(0.4f * PI_F) / 16.0f;

    #pragma unroll 1
    for (int t = 0; t < 10; t++) {
        float4 par = s_par[t];   // a_th, a_r, l_th, l_r

        float T0 = tanh_fast(u0);
        float T1 = tanh_fast(u1);
        float th_rad = T0 * (60.0f * PI_F / 180.0f);
        float sth, cth;
        __sincosf(th_rad, &sth, &cth);
        float q = fmaf(-0.2f, T1 + 1.0f, 0.5f * sth);

        float Pr = TWOPI * (q - rintf(q));
        float sP, cP;
        __sincosf(Pr, &sP, &cP);
        float twocP  = cP + cP;
        float twoc2P = fmaf(twocP, twocP, -2.0f);     // 2*cos(2P)
        u64 aP = pk2(twoc2P, twoc2P);
        u64 aN = pk2(-twoc2P, -twoc2P);

        // step coefficients computed BEFORE v (off the critical path)
        float sech0 = fmaf(-T0, T0, 1.0f);
        float sech1 = fmaf(-T1, T1, 1.0f);
        float cg_th = C_GTH * cth * sech0;
        float cg_r  = C_GR * sech1;
        float acg_th = par.x * cg_th;
        float acg_r  = par.y * cg_r;

        // starting pairs: w0 = (s(a0), s(a0+P)), w1 = (s(a0+2P), s(a0+3P))
        float f = k0f * q;
        float a0 = TWOPI * (f - rintf(f));
        float s0_, c0_;
        __sincosf(a0, &s0_, &c0_);
        float s1_ = fmaf(s0_, cP, c0_ * sP);
        float c1_ = fmaf(c0_, cP, -(s0_ * sP));
        float s2_ = fmaf(twocP, s1_, -s0_);
        float c2_ = fmaf(twocP, c1_, -c0_);
        float s3_ = fmaf(twocP, s2_, -s1_);
        float c3_ = fmaf(twocP, c2_, -c1_);

        u64 psS = pk2(s0_, s1_), psC = pk2(c0_, c1_);   // w_0
        u64 cuS = pk2(s2_, s3_), cuC = pk2(c2_, c3_);   // w_1

        // m = 0, 1 (init accumulators with mul: no zero-pack)
        u64 accS = f2mul(kzre[0], psS);
        u64 accC = f2mul(knzim[0], psC);
        accS = f2fma(kzre[1], cuS, accS);
        accC = f2fma(knzim[1], cuC, accC);
        // m = 2..7: advance Chebyshev (alpha alternates -,+,-,+,-,+), accumulate
        #pragma unroll
        for (int m = 2; m < 8; m++) {
            u64 alpha = (m & 1) ? aP : aN;
            u64 nS = f2fma(alpha, cuS, psS);
            u64 nC = f2fma(alpha, cuC, psC);
            psS = cuS; cuS = nS;
            psC = cuC; cuC = nC;
            accS = f2fma(kzre[m], cuS, accS);
            accC = f2fma(knzim[m], cuC, accC);
        }

        u64 v2 = f2add(accS, accC);
        float vlo, vhi;
        upk2(v2, vlo, vhi);
        float v = vlo + vhi;
        #pragma unroll
        for (int o = 8; o > 0; o >>= 1)
            v += __shfl_xor_sync(0xffffffffu, v, o);

        float g_th = cg_th * v;
        float g_r  = cg_r * v;
        float den_th = fmaxf(fabsf(g_th), 1e-6f) + par.z;
        float den_r  = fmaxf(fabsf(g_r),  1e-6f) + par.w;
        float st_th = clampf(acg_th * v * __fdividef(1.0f, den_th), -0.1f, 0.1f);
        float st_r  = clampf(acg_r  * v * __fdividef(1.0f, den_r),  -0.1f, 0.1f);
        u0 -= st_th;
        u1 -= st_r;
    }

    if (hl == 0) {
        float T0 = tanh_fast(u0);
        float T1 = tanh_fast(u1);
        float2 o;
        o.x = 60.0f * T0;
        o.y = 1000.0f * (T1 + 1.0f);
        reinterpret_cast<float2*>(out)[row] = o;
    }
}

extern "C" void kernel_launch(void* const* d_in, const int* in_sizes, int n_in,
                              void* d_out, int out_size) {
    const float* z_real    = (const float*)d_in[0];
    const float* z_imag    = (const float*)d_in[1];
    const float* theta0    = (const float*)d_in[2];
    const float* r0        = (const float*)d_in[3];
    const float* a_th_raw  = (const float*)d_in[4];
    const float* a_r_raw   = (const float*)d_in[5];
    const float* l_th_raw  = (const float*)d_in[6];
    const float* l_r_raw   = (const float*)d_in[7];
    float* out = (float*)d_out;

    int B = in_sizes[2];
    int nwarps = (B + 1) / 2;
    int threads = 128;
    int blocks = (nwarps * 32 + threads - 1) / threads;
    refiner_kernel<<<blocks, threads>>>(z_real, z_imag, theta0, r0,
                                        a_th_raw, a_r_raw, l_th_raw, l_r_raw,
                                        out, B);
}